// round 16
// baseline (speedup 1.0000x reference)
#include <cuda_runtime.h>
#include <cuda_bf16.h>
#include <cstdint>

#define N_NODES 50000
#define N_EDGES 500000
#define EMB     128
#define HALF_N  25000
#define HALF_ELEMS 3200000u
#define INV_KEEP (1.0f/0.9f)
#define NUM_TILES ((N_EDGES + 127) / 128)

__device__ float g_acc[(size_t)N_NODES * EMB];   // scatter accumulator
__device__ float g_hid[(size_t)N_NODES * EMB];   // H' = hidden @ Wm[0:128] + bm

typedef unsigned long long ull;

// ---------- packed f32x2 helpers ----------
__device__ __forceinline__ ull pack2(float lo, float hi) {
    ull r; asm("mov.b64 %0, {%1, %2};" : "=l"(r) : "f"(lo), "f"(hi)); return r;
}
__device__ __forceinline__ void unpack2(ull v, float& lo, float& hi) {
    asm("mov.b64 {%0, %1}, %2;" : "=f"(lo), "=f"(hi) : "l"(v));
}
__device__ __forceinline__ ull ffma2(ull a, ull b, ull c) {
    ull d; asm("fma.rn.f32x2 %0, %1, %2, %3;" : "=l"(d) : "l"(a), "l"(b), "l"(c));
    return d;
}
__device__ __forceinline__ void red_add_v4(float* addr, float4 v) {
    asm volatile("red.global.add.v4.f32 [%0], {%1, %2, %3, %4};"
                 :: "l"(addr), "f"(v.x), "f"(v.y), "f"(v.z), "f"(v.w) : "memory");
}

// ---------- JAX threefry2x32, key (0,42), partitionable ----------
__device__ __forceinline__ void tf2x32_42(unsigned c0, unsigned c1, unsigned& o0, unsigned& o1) {
    const unsigned k0 = 0u, k1 = 42u, k2 = 0x1BD11BDAu ^ 42u;
    unsigned x0 = c0 + k0, x1 = c1 + k1;
#define TF_R(r) { x0 += x1; x1 = __funnelshift_l(x1, x1, (r)); x1 ^= x0; }
#define TF_G0   TF_R(13) TF_R(15) TF_R(26) TF_R(6)
#define TF_G1   TF_R(17) TF_R(29) TF_R(16) TF_R(24)
    TF_G0; x0 += k1; x1 += k2 + 1u;
    TF_G1; x0 += k2; x1 += k0 + 2u;
    TF_G0; x0 += k0; x1 += k1 + 3u;
    TF_G1; x0 += k1; x1 += k2 + 4u;
    TF_G0; x0 += k2; x1 += k0 + 5u;
#undef TF_R
#undef TF_G0
#undef TF_G1
    o0 = x0; o1 = x1;
}
__device__ __forceinline__ float tf_uniform(unsigned b) {
    return __uint_as_float((b >> 9) | 0x3f800000u) - 1.0f;
}
__device__ __forceinline__ unsigned tf_bits_part(unsigned idx) {
    unsigned a, b; tf2x32_42(0u, idx, a, b); return a ^ b;
}

// ================= KP: H' = hidden @ Wm[0:128] + bm  (+ g_acc = boundary) =========
// R9 version (measured 55.3us): 128-row tiles, 1 CTA/SM, k0 copy folded in.
#define KP_SMEM ((128*128 + 128*128) * 4)

__global__ void __launch_bounds__(256, 1) kp_hid(
    const float* __restrict__ hidden, const float* __restrict__ Wm,
    const float* __restrict__ bm, const float* __restrict__ boundary)
{
    extern __shared__ float sm[];
    float* As = sm;              // [128k][128row]
    float* Bs = sm + 128 * 128;  // [128k][128col]

    const int t = threadIdx.x;
    const int base = blockIdx.x * 128;

    // fold of old k0: copy boundary -> g_acc for this tile's rows
#pragma unroll
    for (int i = 0; i < 16; ++i) {
        int g = blockIdx.x * 4096 + t + i * 256;
        if (g < N_NODES * EMB / 4)
            reinterpret_cast<float4*>(g_acc)[g] =
                reinterpret_cast<const float4*>(boundary)[g];
    }

    // Bs = Wm rows 0..127 — linear copy
#pragma unroll
    for (int i = 0; i < 16; ++i)
        ((float4*)Bs)[t + i * 256] = ((const float4*)Wm)[t + i * 256];

    // As: transpose-stage. thread: row lr = t&127, k-half = t>>7
    {
        int lr = t & 127;
        int gr = base + lr; if (gr >= N_NODES) gr = N_NODES - 1;
        const float* hrow = &hidden[(size_t)gr * EMB];
#pragma unroll
        for (int j = 0; j < 16; ++j) {
            int k0 = (t >> 7) * 64 + j * 4;
            float4 v = *(const float4*)&hrow[k0];
            As[(k0 + 0) * 128 + lr] = v.x;
            As[(k0 + 1) * 128 + lr] = v.y;
            As[(k0 + 2) * 128 + lr] = v.z;
            As[(k0 + 3) * 128 + lr] = v.w;
        }
    }
    __syncthreads();

    const int te = t >> 4, tc = t & 15;
    float4 b0 = *(const float4*)&bm[tc * 8];
    float4 b1 = *(const float4*)&bm[tc * 8 + 4];
    ull acc[4][8];
#pragma unroll
    for (int er = 0; er < 4; ++er) {
        acc[er][0] = pack2(b0.x, b0.x); acc[er][1] = pack2(b0.y, b0.y);
        acc[er][2] = pack2(b0.z, b0.z); acc[er][3] = pack2(b0.w, b0.w);
        acc[er][4] = pack2(b1.x, b1.x); acc[er][5] = pack2(b1.y, b1.y);
        acc[er][6] = pack2(b1.z, b1.z); acc[er][7] = pack2(b1.w, b1.w);
    }

#pragma unroll 4
    for (int k = 0; k < 128; ++k) {
        const ulonglong2* ap = (const ulonglong2*)&As[k * 128 + te * 8];
        ulonglong2 a01 = ap[0], a23 = ap[1];
        float4 q0 = *(const float4*)&Bs[k * 128 + tc * 8];
        float4 q1 = *(const float4*)&Bs[k * 128 + tc * 8 + 4];
        ull bp[8] = {pack2(q0.x, q0.x), pack2(q0.y, q0.y), pack2(q0.z, q0.z), pack2(q0.w, q0.w),
                     pack2(q1.x, q1.x), pack2(q1.y, q1.y), pack2(q1.z, q1.z), pack2(q1.w, q1.w)};
        ull a[4] = {a01.x, a01.y, a23.x, a23.y};
#pragma unroll
        for (int er = 0; er < 4; ++er)
#pragma unroll
            for (int c = 0; c < 8; ++c)
                acc[er][c] = ffma2(a[er], bp[c], acc[er][c]);
    }

#pragma unroll
    for (int er = 0; er < 4; ++er) {
        int r0 = base + te * 8 + er * 2;
        float lo[8], hi[8];
#pragma unroll
        for (int c = 0; c < 8; ++c) unpack2(acc[er][c], lo[c], hi[c]);
        if (r0 < N_NODES) {
            *(float4*)&g_hid[(size_t)r0 * EMB + tc * 8]     = make_float4(lo[0], lo[1], lo[2], lo[3]);
            *(float4*)&g_hid[(size_t)r0 * EMB + tc * 8 + 4] = make_float4(lo[4], lo[5], lo[6], lo[7]);
        }
        if (r0 + 1 < N_NODES) {
            *(float4*)&g_hid[(size_t)(r0 + 1) * EMB + tc * 8]     = make_float4(hi[0], hi[1], hi[2], hi[3]);
            *(float4*)&g_hid[(size_t)(r0 + 1) * EMB + tc * 8 + 4] = make_float4(hi[4], hi[5], hi[6], hi[7]);
        }
    }
}

// ================= K1: edge GEMM, scheme-2 (no packing MOVs in mainloop) ==========
// As2: [64k][256] edge-DUPLICATED floats (As2[k][2e]=As2[k][2e+1]=A[e][k]) -> a-pairs
// load directly as ull. Bs row-major -> col-pairs load directly as ull.
// Thread (te=t>>4: edges te*8..+8, tc=t&15: col-pairs tc*4..+4 i.e. cols tc*8..+8).
#define K1_SMEM ((64*256 + 64*128) * 4 + 2*128*4)   // 64KB + 32KB + 1KB

__global__ void __launch_bounds__(256, 2) k1_msg(
    const int* __restrict__ eidx, const float* __restrict__ eattr,
    const float* __restrict__ etime, const float* __restrict__ Wm)
{
    extern __shared__ float sm[];
    float* As2 = sm;               // [64][256] duplicated
    float* Bs  = sm + 64 * 256;    // [64][128]
    int* src_s = (int*)(sm + 64 * 256 + 64 * 128);
    int* dst_s = src_s + 128;

    const int t = threadIdx.x;
    const int e0 = blockIdx.x * 128;

    // Bs = Wm rows 128..191 — linear copy (2048 float4)
    {
        const float4* Wq = (const float4*)(Wm + 128 * EMB);
#pragma unroll
        for (int i = 0; i < 8; ++i)
            ((float4*)Bs)[t + i * 256] = Wq[t + i * 256];
    }
    // edge indices
    if (t < 128) {
        int e = e0 + t;
        src_s[t] = (e < N_EDGES) ? eidx[e] : 0;
    } else {
        int e = e0 + t - 128;
        dst_s[t - 128] = (e < N_EDGES) ? eidx[N_EDGES + e] : -1;
    }
    // As2: gather edge features, transpose + duplicate. thread: edge e=t&127, sel=t>>7
    {
        int e = t & 127;
        int ge = e0 + e;
        int gec = (ge < N_EDGES) ? ge : (N_EDGES - 1);
        int sel = t >> 7;
        const float* ptr = sel ? &etime[(size_t)gec * 32] : &eattr[(size_t)gec * 32];
        ull* A8 = (ull*)As2;       // ull index = k*128 + e
#pragma unroll
        for (int j = 0; j < 8; ++j) {
            float4 v = *(const float4*)&ptr[j * 4];
            int k0 = sel * 32 + j * 4;
            A8[(k0 + 0) * 128 + e] = pack2(v.x, v.x);
            A8[(k0 + 1) * 128 + e] = pack2(v.y, v.y);
            A8[(k0 + 2) * 128 + e] = pack2(v.z, v.z);
            A8[(k0 + 3) * 128 + e] = pack2(v.w, v.w);
        }
    }
    __syncthreads();

    const int te = t >> 4, tc = t & 15;
    ull acc[8][4];
#pragma unroll
    for (int e = 0; e < 8; ++e)
#pragma unroll
        for (int q = 0; q < 4; ++q) acc[e][q] = 0ull;

#pragma unroll 4
    for (int k = 0; k < 64; ++k) {
        const ulonglong2* ap = (const ulonglong2*)&As2[k * 256 + te * 16];
        ulonglong2 a01 = ap[0], a23 = ap[1], a45 = ap[2], a67 = ap[3];
        const ulonglong2* bp = (const ulonglong2*)&Bs[k * 128 + tc * 8];
        ulonglong2 b01 = bp[0], b23 = bp[1];
        ull a[8] = {a01.x, a01.y, a23.x, a23.y, a45.x, a45.y, a67.x, a67.y};
        ull b[4] = {b01.x, b01.y, b23.x, b23.y};
#pragma unroll
        for (int e = 0; e < 8; ++e)
#pragma unroll
            for (int q = 0; q < 4; ++q)
                acc[e][q] = ffma2(a[e], b[q], acc[e][q]);
    }

    // epilogue: msg = relu(H'[src] + acc); scatter-add to g_acc[dst]
#pragma unroll
    for (int e = 0; e < 8; ++e) {
        int le = te * 8 + e;
        int sidx = src_s[le];
        int d = dst_s[le];
        const float* hp = &g_hid[(size_t)sidx * EMB + tc * 8];
        float4 h0 = *(const float4*)hp;
        float4 h1 = *(const float4*)(hp + 4);
        float c[8];
#pragma unroll
        for (int q = 0; q < 4; ++q) unpack2(acc[e][q], c[2 * q], c[2 * q + 1]);
        float4 o0 = make_float4(fmaxf(c[0] + h0.x, 0.f), fmaxf(c[1] + h0.y, 0.f),
                                fmaxf(c[2] + h0.z, 0.f), fmaxf(c[3] + h0.w, 0.f));
        float4 o1 = make_float4(fmaxf(c[4] + h1.x, 0.f), fmaxf(c[5] + h1.y, 0.f),
                                fmaxf(c[6] + h1.z, 0.f), fmaxf(c[7] + h1.w, 0.f));
        if (d >= 0) {
            float* base = &g_acc[(size_t)d * EMB + tc * 8];
            red_add_v4(base, o0);
            red_add_v4(base + 4, o1);
        }
    }
}

// ================= K2: node GEMM + LN + relu + dropout ==================
#define K2_SMEM ((128*64 + 128*128) * 4)

__global__ void __launch_bounds__(256, 2) k2_node(
    const float* __restrict__ Wl, const float* __restrict__ bl,
    const float* __restrict__ gamma, const float* __restrict__ beta,
    float* __restrict__ out)
{
    extern __shared__ float sm[];
    float* As = sm;              // [128][64] k-major
    float* Bs = sm + 128 * 64;   // [128][128]

    const int t  = threadIdx.x;
    const int tr = t >> 5, tc = t & 31;
    const int base = blockIdx.x * 32;

#pragma unroll
    for (int i = 0; i < 16; ++i) {
        int idx = t + i * 256;
        int r = idx >> 5, q = idx & 31;
        *(float4*)&Bs[r * EMB + q * 4] = *(const float4*)&Wl[r * EMB + q * 4];
    }
    {
        int lr = t & 63;
        int pr = base + (lr >> 1);
        int grow = ((pr < HALF_N) ? pr : (HALF_N - 1)) + ((lr & 1) ? HALF_N : 0);
#pragma unroll
        for (int j = 0; j < 8; ++j) {
            int q = (t >> 6) * 8 + j;
            float4 v = *(const float4*)&g_acc[(size_t)grow * EMB + q * 4];
            As[(q * 4 + 0) * 64 + lr] = v.x;
            As[(q * 4 + 1) * 64 + lr] = v.y;
            As[(q * 4 + 2) * 64 + lr] = v.z;
            As[(q * 4 + 3) * 64 + lr] = v.w;
        }
    }
    float4 blv = *(const float4*)&bl[tc * 4];
    ull acc[4][4];
#pragma unroll
    for (int p = 0; p < 4; ++p) {
        acc[p][0] = pack2(blv.x, blv.x); acc[p][1] = pack2(blv.y, blv.y);
        acc[p][2] = pack2(blv.z, blv.z); acc[p][3] = pack2(blv.w, blv.w);
    }
    __syncthreads();

#pragma unroll 8
    for (int k = 0; k < 128; ++k) {
        const ulonglong2* ap = (const ulonglong2*)&As[k * 64 + tr * 8];
        ulonglong2 a01 = ap[0], a23 = ap[1];
        float4 b = *(const float4*)&Bs[k * EMB + tc * 4];
        ull b0 = pack2(b.x, b.x), b1 = pack2(b.y, b.y);
        ull b2 = pack2(b.z, b.z), b3 = pack2(b.w, b.w);
        ull a[4] = {a01.x, a01.y, a23.x, a23.y};
#pragma unroll
        for (int p = 0; p < 4; ++p) {
            acc[p][0] = ffma2(a[p], b0, acc[p][0]);
            acc[p][1] = ffma2(a[p], b1, acc[p][1]);
            acc[p][2] = ffma2(a[p], b2, acc[p][2]);
            acc[p][3] = ffma2(a[p], b3, acc[p][3]);
        }
    }

    float4 gv = *(const float4*)&gamma[tc * 4];
    float4 bv = *(const float4*)&beta[tc * 4];
    float ga[4] = {gv.x, gv.y, gv.z, gv.w};
    float be[4] = {bv.x, bv.y, bv.z, bv.w};

#pragma unroll
    for (int p = 0; p < 4; ++p) {
        float lo[4], hi[4];
#pragma unroll
        for (int j = 0; j < 4; ++j) unpack2(acc[p][j], lo[j], hi[j]);

        int rlow = base + tr * 4 + p;

        unsigned bits0[4], bits1[4];
#pragma unroll
        for (int j = 0; j < 4; ++j) {
            unsigned idx0 = (unsigned)(rlow * EMB + tc * 4 + j);
            bits0[j] = tf_bits_part(idx0);
            bits1[j] = tf_bits_part(idx0 + HALF_ELEMS);
        }

        float s0 = lo[0] + lo[1] + lo[2] + lo[3];
        float q0 = lo[0]*lo[0] + lo[1]*lo[1] + lo[2]*lo[2] + lo[3]*lo[3];
        float s1 = hi[0] + hi[1] + hi[2] + hi[3];
        float q1 = hi[0]*hi[0] + hi[1]*hi[1] + hi[2]*hi[2] + hi[3]*hi[3];
#pragma unroll
        for (int off = 16; off; off >>= 1) {
            s0 += __shfl_xor_sync(0xffffffffu, s0, off);
            q0 += __shfl_xor_sync(0xffffffffu, q0, off);
            s1 += __shfl_xor_sync(0xffffffffu, s1, off);
            q1 += __shfl_xor_sync(0xffffffffu, q1, off);
        }
        float m0 = s0 * (1.0f / EMB);
        float r0 = rsqrtf(q0 * (1.0f / EMB) - m0 * m0 + 1e-5f);
        float m1 = s1 * (1.0f / EMB);
        float r1 = rsqrtf(q1 * (1.0f / EMB) - m1 * m1 + 1e-5f);

        float o0[4], o1[4];
#pragma unroll
        for (int j = 0; j < 4; ++j) {
            float y0 = fmaxf((lo[j] - m0) * r0 * ga[j] + be[j], 0.f);
            float y1 = fmaxf((hi[j] - m1) * r1 * ga[j] + be[j], 0.f);
            o0[j] = (tf_uniform(bits0[j]) < 0.9f) ? y0 * INV_KEEP : 0.f;
            o1[j] = (tf_uniform(bits1[j]) < 0.9f) ? y1 * INV_KEEP : 0.f;
        }
        if (rlow < HALF_N) {
            *(float4*)&out[(size_t)rlow * EMB + tc * 4] =
                make_float4(o0[0], o0[1], o0[2], o0[3]);
            *(float4*)&out[(size_t)(rlow + HALF_N) * EMB + tc * 4] =
                make_float4(o1[0], o1[1], o1[2], o1[3]);
        }
    }
}

// ================= launch ==================
extern "C" void kernel_launch(void* const* d_in, const int* in_sizes, int n_in,
                              void* d_out, int out_size) {
    (void)in_sizes; (void)n_in; (void)out_size;
    const float* hidden = (const float*)d_in[0];
    const int*   eidx   = (const int*)  d_in[1];
    const float* eattr  = (const float*)d_in[2];
    const float* etime  = (const float*)d_in[3];
    const float* bc     = (const float*)d_in[4];
    const float* Wm     = (const float*)d_in[5];
    const float* bm     = (const float*)d_in[6];
    const float* Wl     = (const float*)d_in[7];
    const float* bl     = (const float*)d_in[8];
    const float* gam    = (const float*)d_in[9];
    const float* bet    = (const float*)d_in[10];
    float* out = (float*)d_out;

    cudaFuncSetAttribute((const void*)kp_hid,
                         cudaFuncAttributeMaxDynamicSharedMemorySize, KP_SMEM);
    cudaFuncSetAttribute((const void*)k1_msg,
                         cudaFuncAttributeMaxDynamicSharedMemorySize, K1_SMEM);
    cudaFuncSetAttribute((const void*)k2_node,
                         cudaFuncAttributeMaxDynamicSharedMemorySize, K2_SMEM);

    kp_hid<<<(N_NODES + 127) / 128, 256, KP_SMEM>>>(hidden, Wm, bm, bc);
    k1_msg<<<NUM_TILES, 256, K1_SMEM>>>(eidx, eattr, etime, Wm);
    k2_node<<<(HALF_N + 31) / 32, 256, K2_SMEM>>>(Wl, bl, gam, bet, out);
}

// round 17
// speedup vs baseline: 1.1993x; 1.1993x over previous
#include <cuda_runtime.h>
#include <cuda_bf16.h>
#include <cstdint>

#define N_NODES 50000
#define N_EDGES 500000
#define EMB     128
#define HALF_N  25000
#define HALF_ELEMS 3200000u
#define INV_KEEP (1.0f/0.9f)
#define NUM_TILES ((N_EDGES + 127) / 128)

__device__ float g_acc[(size_t)N_NODES * EMB];   // scatter accumulator
__device__ float g_hid[(size_t)N_NODES * EMB];   // H' = hidden @ Wm[0:128] + bm

typedef unsigned long long ull;

// ---------- packed f32x2 helpers ----------
__device__ __forceinline__ ull pack2(float lo, float hi) {
    ull r; asm("mov.b64 %0, {%1, %2};" : "=l"(r) : "f"(lo), "f"(hi)); return r;
}
__device__ __forceinline__ void unpack2(ull v, float& lo, float& hi) {
    asm("mov.b64 {%0, %1}, %2;" : "=f"(lo), "=f"(hi) : "l"(v));
}
__device__ __forceinline__ ull ffma2(ull a, ull b, ull c) {
    ull d; asm("fma.rn.f32x2 %0, %1, %2, %3;" : "=l"(d) : "l"(a), "l"(b), "l"(c));
    return d;
}
__device__ __forceinline__ void red_add_v2(float* addr, float x, float y) {
    asm volatile("red.global.add.v2.f32 [%0], {%1, %2};"
                 :: "l"(addr), "f"(x), "f"(y) : "memory");
}

// bf16 split of 8 consecutive fp32 -> 4 b32 hi-pairs + 4 b32 lo-pairs
__device__ __forceinline__ void cvt8_split(const float* v, uint32_t* hi, uint32_t* lo) {
#pragma unroll
    for (int i = 0; i < 4; ++i) {
        float a = v[2 * i], b = v[2 * i + 1];
        __nv_bfloat16 ah = __float2bfloat16(a);
        __nv_bfloat16 bh = __float2bfloat16(b);
        __nv_bfloat16 al = __float2bfloat16(a - __bfloat162float(ah));
        __nv_bfloat16 bl = __float2bfloat16(b - __bfloat162float(bh));
        hi[i] = ((uint32_t)__bfloat16_as_ushort(bh) << 16) | __bfloat16_as_ushort(ah);
        lo[i] = ((uint32_t)__bfloat16_as_ushort(bl) << 16) | __bfloat16_as_ushort(al);
    }
}

// mma.sync m16n8k16 row.col bf16 -> f32 accumulate
__device__ __forceinline__ void mma16816(float* d, const uint32_t* a,
                                         uint32_t b0, uint32_t b1) {
    asm volatile(
        "mma.sync.aligned.m16n8k16.row.col.f32.bf16.bf16.f32 "
        "{%0,%1,%2,%3}, {%4,%5,%6,%7}, {%8,%9}, {%0,%1,%2,%3};"
        : "+f"(d[0]), "+f"(d[1]), "+f"(d[2]), "+f"(d[3])
        : "r"(a[0]), "r"(a[1]), "r"(a[2]), "r"(a[3]), "r"(b0), "r"(b1));
}

// ---------- JAX threefry2x32, key (0,42), partitionable ----------
__device__ __forceinline__ void tf2x32_42(unsigned c0, unsigned c1, unsigned& o0, unsigned& o1) {
    const unsigned k0 = 0u, k1 = 42u, k2 = 0x1BD11BDAu ^ 42u;
    unsigned x0 = c0 + k0, x1 = c1 + k1;
#define TF_R(r) { x0 += x1; x1 = __funnelshift_l(x1, x1, (r)); x1 ^= x0; }
#define TF_G0   TF_R(13) TF_R(15) TF_R(26) TF_R(6)
#define TF_G1   TF_R(17) TF_R(29) TF_R(16) TF_R(24)
    TF_G0; x0 += k1; x1 += k2 + 1u;
    TF_G1; x0 += k2; x1 += k0 + 2u;
    TF_G0; x0 += k0; x1 += k1 + 3u;
    TF_G1; x0 += k1; x1 += k2 + 4u;
    TF_G0; x0 += k2; x1 += k0 + 5u;
#undef TF_R
#undef TF_G0
#undef TF_G1
    o0 = x0; o1 = x1;
}
__device__ __forceinline__ float tf_uniform(unsigned b) {
    return __uint_as_float((b >> 9) | 0x3f800000u) - 1.0f;
}
__device__ __forceinline__ unsigned tf_bits_part(unsigned idx) {
    unsigned a, b; tf2x32_42(0u, idx, a, b); return a ^ b;
}

// ================= KP: H' = hidden @ Wm[0:128] + bm  (+ g_acc = boundary) =========
// measured 55us: 128-row tiles, 1 CTA/SM, k0 copy folded in.
#define KP_SMEM ((128*128 + 128*128) * 4)

__global__ void __launch_bounds__(256, 1) kp_hid(
    const float* __restrict__ hidden, const float* __restrict__ Wm,
    const float* __restrict__ bm, const float* __restrict__ boundary)
{
    extern __shared__ float sm[];
    float* As = sm;              // [128k][128row]
    float* Bs = sm + 128 * 128;  // [128k][128col]

    const int t = threadIdx.x;
    const int base = blockIdx.x * 128;

#pragma unroll
    for (int i = 0; i < 16; ++i) {
        int g = blockIdx.x * 4096 + t + i * 256;
        if (g < N_NODES * EMB / 4)
            reinterpret_cast<float4*>(g_acc)[g] =
                reinterpret_cast<const float4*>(boundary)[g];
    }

#pragma unroll
    for (int i = 0; i < 16; ++i)
        ((float4*)Bs)[t + i * 256] = ((const float4*)Wm)[t + i * 256];

    {
        int lr = t & 127;
        int gr = base + lr; if (gr >= N_NODES) gr = N_NODES - 1;
        const float* hrow = &hidden[(size_t)gr * EMB];
#pragma unroll
        for (int j = 0; j < 16; ++j) {
            int k0 = (t >> 7) * 64 + j * 4;
            float4 v = *(const float4*)&hrow[k0];
            As[(k0 + 0) * 128 + lr] = v.x;
            As[(k0 + 1) * 128 + lr] = v.y;
            As[(k0 + 2) * 128 + lr] = v.z;
            As[(k0 + 3) * 128 + lr] = v.w;
        }
    }
    __syncthreads();

    const int te = t >> 4, tc = t & 15;
    float4 b0 = *(const float4*)&bm[tc * 8];
    float4 b1 = *(const float4*)&bm[tc * 8 + 4];
    ull acc[4][8];
#pragma unroll
    for (int er = 0; er < 4; ++er) {
        acc[er][0] = pack2(b0.x, b0.x); acc[er][1] = pack2(b0.y, b0.y);
        acc[er][2] = pack2(b0.z, b0.z); acc[er][3] = pack2(b0.w, b0.w);
        acc[er][4] = pack2(b1.x, b1.x); acc[er][5] = pack2(b1.y, b1.y);
        acc[er][6] = pack2(b1.z, b1.z); acc[er][7] = pack2(b1.w, b1.w);
    }

#pragma unroll 4
    for (int k = 0; k < 128; ++k) {
        const ulonglong2* ap = (const ulonglong2*)&As[k * 128 + te * 8];
        ulonglong2 a01 = ap[0], a23 = ap[1];
        float4 q0 = *(const float4*)&Bs[k * 128 + tc * 8];
        float4 q1 = *(const float4*)&Bs[k * 128 + tc * 8 + 4];
        ull bp[8] = {pack2(q0.x, q0.x), pack2(q0.y, q0.y), pack2(q0.z, q0.z), pack2(q0.w, q0.w),
                     pack2(q1.x, q1.x), pack2(q1.y, q1.y), pack2(q1.z, q1.z), pack2(q1.w, q1.w)};
        ull a[4] = {a01.x, a01.y, a23.x, a23.y};
#pragma unroll
        for (int er = 0; er < 4; ++er)
#pragma unroll
            for (int c = 0; c < 8; ++c)
                acc[er][c] = ffma2(a[er], bp[c], acc[er][c]);
    }

#pragma unroll
    for (int er = 0; er < 4; ++er) {
        int r0 = base + te * 8 + er * 2;
        float lo[8], hi[8];
#pragma unroll
        for (int c = 0; c < 8; ++c) unpack2(acc[er][c], lo[c], hi[c]);
        if (r0 < N_NODES) {
            *(float4*)&g_hid[(size_t)r0 * EMB + tc * 8]     = make_float4(lo[0], lo[1], lo[2], lo[3]);
            *(float4*)&g_hid[(size_t)r0 * EMB + tc * 8 + 4] = make_float4(lo[4], lo[5], lo[6], lo[7]);
        }
        if (r0 + 1 < N_NODES) {
            *(float4*)&g_hid[(size_t)(r0 + 1) * EMB + tc * 8]     = make_float4(hi[0], hi[1], hi[2], hi[3]);
            *(float4*)&g_hid[(size_t)(r0 + 1) * EMB + tc * 8 + 4] = make_float4(hi[4], hi[5], hi[6], hi[7]);
        }
    }
}

// ================= K1: mma.sync bf16-split edge GEMM + gather + relu + scatter =====
// Tile 128 edges x 128 cols, K=64, 8 warps (warp = 16 edges x 128 cols).
// A smem [128e][64k] bf16, 144B row stride (16B pad -> conflict-free LDS.32 frags).
// B smem TRANSPOSED [128n][64k] bf16, 144B stride. 3-term split: AhBh + AhBl + AlBh.
#define K1_AH   0
#define K1_AL   (128 * 144)
#define K1_BH   (2 * 128 * 144)
#define K1_BW   (3 * 128 * 144)
#define K1_SRC  (4 * 128 * 144)
#define K1_DSTO (4 * 128 * 144 + 512)
#define K1_SMEM (4 * 128 * 144 + 1024)

__global__ void __launch_bounds__(256, 2) k1_msg(
    const int* __restrict__ eidx, const float* __restrict__ eattr,
    const float* __restrict__ etime, const float* __restrict__ Wm)
{
    extern __shared__ char smc[];
    const int t = threadIdx.x;
    const int e0 = blockIdx.x * 128;

    int* src_s = (int*)(smc + K1_SRC);
    int* dst_s = (int*)(smc + K1_DSTO);

    // ---- stage B transposed + split (once per CTA): thread n=t>>1, k-half=t&1 ----
    {
        const int n = t >> 1, half = t & 1;
#pragma unroll
        for (int q = 0; q < 4; ++q) {
            int k0 = half * 32 + q * 8;
            float v[8];
#pragma unroll
            for (int i = 0; i < 8; ++i)
                v[i] = Wm[(size_t)(128 + k0 + i) * EMB + n];
            uint32_t hi[4], lo[4];
            cvt8_split(v, hi, lo);
            int off = n * 144 + k0 * 2;
            *(uint4*)(smc + K1_BH + off) = make_uint4(hi[0], hi[1], hi[2], hi[3]);
            *(uint4*)(smc + K1_BW + off) = make_uint4(lo[0], lo[1], lo[2], lo[3]);
        }
    }
    // ---- edge indices ----
    if (t < 128) {
        int e = e0 + t;
        src_s[t] = (e < N_EDGES) ? eidx[e] : 0;
    } else {
        int e = e0 + t - 128;
        dst_s[t - 128] = (e < N_EDGES) ? eidx[N_EDGES + e] : -1;
    }
    // ---- stage A + split: thread edge e=t&127, k-half sel=t>>7 ----
    {
        const int e = t & 127, sel = t >> 7;
        const int ge = e0 + e;
        const int gec = (ge < N_EDGES) ? ge : (N_EDGES - 1);
        const float* ptr = sel ? &etime[(size_t)gec * 32] : &eattr[(size_t)gec * 32];
#pragma unroll
        for (int j = 0; j < 4; ++j) {
            float4 u0 = *(const float4*)&ptr[j * 8];
            float4 u1 = *(const float4*)&ptr[j * 8 + 4];
            float v[8] = {u0.x, u0.y, u0.z, u0.w, u1.x, u1.y, u1.z, u1.w};
            uint32_t hi[4], lo[4];
            cvt8_split(v, hi, lo);
            int k0 = sel * 32 + j * 8;
            int off = e * 144 + k0 * 2;
            *(uint4*)(smc + K1_AH + off) = make_uint4(hi[0], hi[1], hi[2], hi[3]);
            *(uint4*)(smc + K1_AL + off) = make_uint4(lo[0], lo[1], lo[2], lo[3]);
        }
    }
    __syncthreads();

    // ---- MMA mainloop ----
    const int lane = t & 31, w = t >> 5;
    const int ew = w * 16;
    const int ar = ew + (lane >> 2);          // a-frag row (and +8)
    const int kb4 = (lane & 3) * 4;           // a/b-frag k byte offset within 16k blk

    // hoist A fragments for all 4 k-blocks (hi & lo)
    uint32_t ah[4][4], al[4][4];
#pragma unroll
    for (int kb = 0; kb < 4; ++kb) {
        int b = ar * 144 + kb * 32 + kb4;
        ah[kb][0] = *(const uint32_t*)(smc + K1_AH + b);
        ah[kb][1] = *(const uint32_t*)(smc + K1_AH + b + 8 * 144);
        ah[kb][2] = *(const uint32_t*)(smc + K1_AH + b + 16);
        ah[kb][3] = *(const uint32_t*)(smc + K1_AH + b + 8 * 144 + 16);
        al[kb][0] = *(const uint32_t*)(smc + K1_AL + b);
        al[kb][1] = *(const uint32_t*)(smc + K1_AL + b + 8 * 144);
        al[kb][2] = *(const uint32_t*)(smc + K1_AL + b + 16);
        al[kb][3] = *(const uint32_t*)(smc + K1_AL + b + 8 * 144 + 16);
    }

    // per-lane epilogue rows (fixed across nb)
    const int e1 = ew + (lane >> 2), e2 = e1 + 8;
    const int s1 = src_s[e1], s2 = src_s[e2];
    const int d1 = dst_s[e1], d2 = dst_s[e2];

#pragma unroll
    for (int nb = 0; nb < 16; ++nb) {
        float acc[4] = {0.f, 0.f, 0.f, 0.f};
        const int nB = (nb * 8 + (lane >> 2)) * 144 + kb4;
#pragma unroll
        for (int kb = 0; kb < 4; ++kb) {
            int b = nB + kb * 32;
            uint32_t bh0 = *(const uint32_t*)(smc + K1_BH + b);
            uint32_t bh1 = *(const uint32_t*)(smc + K1_BH + b + 16);
            uint32_t bl0 = *(const uint32_t*)(smc + K1_BW + b);
            uint32_t bl1 = *(const uint32_t*)(smc + K1_BW + b + 16);
            mma16816(acc, ah[kb], bh0, bh1);
            mma16816(acc, ah[kb], bl0, bl1);
            mma16816(acc, al[kb], bh0, bh1);
        }
        // epilogue for 8 cols of this nb
        const int c0 = nb * 8 + (lane & 3) * 2;
        float2 h1 = *(const float2*)&g_hid[(size_t)s1 * EMB + c0];
        float2 h2 = *(const float2*)&g_hid[(size_t)s2 * EMB + c0];
        if (d1 >= 0)
            red_add_v2(&g_acc[(size_t)d1 * EMB + c0],
                       fmaxf(acc[0] + h1.x, 0.f), fmaxf(acc[1] + h1.y, 0.f));
        if (d2 >= 0)
            red_add_v2(&g_acc[(size_t)d2 * EMB + c0],
                       fmaxf(acc[2] + h2.x, 0.f), fmaxf(acc[3] + h2.y, 0.f));
    }
}

// ================= K2: node GEMM + LN + relu + dropout ==================
#define K2_SMEM ((128*64 + 128*128) * 4)

__global__ void __launch_bounds__(256, 2) k2_node(
    const float* __restrict__ Wl, const float* __restrict__ bl,
    const float* __restrict__ gamma, const float* __restrict__ beta,
    float* __restrict__ out)
{
    extern __shared__ float sm[];
    float* As = sm;              // [128][64] k-major
    float* Bs = sm + 128 * 64;   // [128][128]

    const int t  = threadIdx.x;
    const int tr = t >> 5, tc = t & 31;
    const int base = blockIdx.x * 32;

#pragma unroll
    for (int i = 0; i < 16; ++i) {
        int idx = t + i * 256;
        int r = idx >> 5, q = idx & 31;
        *(float4*)&Bs[r * EMB + q * 4] = *(const float4*)&Wl[r * EMB + q * 4];
    }
    {
        int lr = t & 63;
        int pr = base + (lr >> 1);
        int grow = ((pr < HALF_N) ? pr : (HALF_N - 1)) + ((lr & 1) ? HALF_N : 0);
#pragma unroll
        for (int j = 0; j < 8; ++j) {
            int q = (t >> 6) * 8 + j;
            float4 v = *(const float4*)&g_acc[(size_t)grow * EMB + q * 4];
            As[(q * 4 + 0) * 64 + lr] = v.x;
            As[(q * 4 + 1) * 64 + lr] = v.y;
            As[(q * 4 + 2) * 64 + lr] = v.z;
            As[(q * 4 + 3) * 64 + lr] = v.w;
        }
    }
    float4 blv = *(const float4*)&bl[tc * 4];
    ull acc[4][4];
#pragma unroll
    for (int p = 0; p < 4; ++p) {
        acc[p][0] = pack2(blv.x, blv.x); acc[p][1] = pack2(blv.y, blv.y);
        acc[p][2] = pack2(blv.z, blv.z); acc[p][3] = pack2(blv.w, blv.w);
    }
    __syncthreads();

#pragma unroll 8
    for (int k = 0; k < 128; ++k) {
        const ulonglong2* ap = (const ulonglong2*)&As[k * 64 + tr * 8];
        ulonglong2 a01 = ap[0], a23 = ap[1];
        float4 b = *(const float4*)&Bs[k * EMB + tc * 4];
        ull b0 = pack2(b.x, b.x), b1 = pack2(b.y, b.y);
        ull b2 = pack2(b.z, b.z), b3 = pack2(b.w, b.w);
        ull a[4] = {a01.x, a01.y, a23.x, a23.y};
#pragma unroll
        for (int p = 0; p < 4; ++p) {
            acc[p][0] = ffma2(a[p], b0, acc[p][0]);
            acc[p][1] = ffma2(a[p], b1, acc[p][1]);
            acc[p][2] = ffma2(a[p], b2, acc[p][2]);
            acc[p][3] = ffma2(a[p], b3, acc[p][3]);
        }
    }

    float4 gv = *(const float4*)&gamma[tc * 4];
    float4 bv = *(const float4*)&beta[tc * 4];
    float ga[4] = {gv.x, gv.y, gv.z, gv.w};
    float be[4] = {bv.x, bv.y, bv.z, bv.w};

#pragma unroll
    for (int p = 0; p < 4; ++p) {
        float lo[4], hi[4];
#pragma unroll
        for (int j = 0; j < 4; ++j) unpack2(acc[p][j], lo[j], hi[j]);

        int rlow = base + tr * 4 + p;

        unsigned bits0[4], bits1[4];
#pragma unroll
        for (int j = 0; j < 4; ++j) {
            unsigned idx0 = (unsigned)(rlow * EMB + tc * 4 + j);
            bits0[j] = tf_bits_part(idx0);
            bits1[j] = tf_bits_part(idx0 + HALF_ELEMS);
        }

        float s0 = lo[0] + lo[1] + lo[2] + lo[3];
        float q0 = lo[0]*lo[0] + lo[1]*lo[1] + lo[2]*lo[2] + lo[3]*lo[3];
        float s1 = hi[0] + hi[1] + hi[2] + hi[3];
        float q1 = hi[0]*hi[0] + hi[1]*hi[1] + hi[2]*hi[2] + hi[3]*hi[3];
#pragma unroll
        for (int off = 16; off; off >>= 1) {
            s0 += __shfl_xor_sync(0xffffffffu, s0, off);
            q0 += __shfl_xor_sync(0xffffffffu, q0, off);
            s1 += __shfl_xor_sync(0xffffffffu, s1, off);
            q1 += __shfl_xor_sync(0xffffffffu, q1, off);
        }
        float m0 = s0 * (1.0f / EMB);
        float r0 = rsqrtf(q0 * (1.0f / EMB) - m0 * m0 + 1e-5f);
        float m1 = s1 * (1.0f / EMB);
        float r1 = rsqrtf(q1 * (1.0f / EMB) - m1 * m1 + 1e-5f);

        float o0[4], o1[4];
#pragma unroll
        for (int j = 0; j < 4; ++j) {
            float y0 = fmaxf((lo[j] - m0) * r0 * ga[j] + be[j], 0.f);
            float y1 = fmaxf((hi[j] - m1) * r1 * ga[j] + be[j], 0.f);
            o0[j] = (tf_uniform(bits0[j]) < 0.9f) ? y0 * INV_KEEP : 0.f;
            o1[j] = (tf_uniform(bits1[j]) < 0.9f) ? y1 * INV_KEEP : 0.f;
        }
        if (rlow < HALF_N) {
            *(float4*)&out[(size_t)rlow * EMB + tc * 4] =
                make_float4(o0[0], o0[1], o0[2], o0[3]);
            *(float4*)&out[(size_t)(rlow + HALF_N) * EMB + tc * 4] =
                make_float4(o1[0], o1[1], o1[2], o1[3]);
        }
    }
}

// ================= launch ==================
extern "C" void kernel_launch(void* const* d_in, const int* in_sizes, int n_in,
                              void* d_out, int out_size) {
    (void)in_sizes; (void)n_in; (void)out_size;
    const float* hidden = (const float*)d_in[0];
    const int*   eidx   = (const int*)  d_in[1];
    const float* eattr  = (const float*)d_in[2];
    const float* etime  = (const float*)d_in[3];
    const float* bc     = (const float*)d_in[4];
    const float* Wm     = (const float*)d_in[5];
    const float* bm     = (const float*)d_in[6];
    const float* Wl     = (const float*)d_in[7];
    const float* bl     = (const float*)d_in[8];
    const float* gam    = (const float*)d_in[9];
    const float* bet    = (const float*)d_in[10];
    float* out = (float*)d_out;

    cudaFuncSetAttribute((const void*)kp_hid,
                         cudaFuncAttributeMaxDynamicSharedMemorySize, KP_SMEM);
    cudaFuncSetAttribute((const void*)k1_msg,
                         cudaFuncAttributeMaxDynamicSharedMemorySize, K1_SMEM);
    cudaFuncSetAttribute((const void*)k2_node,
                         cudaFuncAttributeMaxDynamicSharedMemorySize, K2_SMEM);

    kp_hid<<<(N_NODES + 127) / 128, 256, KP_SMEM>>>(hidden, Wm, bm, bc);
    k1_msg<<<NUM_TILES, 256, K1_SMEM>>>(eidx, eattr, etime, Wm);
    k2_node<<<(HALF_N + 31) / 32, 256, K2_SMEM>>>(Wl, bl, gam, bet, out);
}